// round 9
// baseline (speedup 1.0000x reference)
#include <cuda_runtime.h>
#include <cstdint>

// Table-batched embedding bag, SUM pooling.
// indices: int32 [T*B*L], offsets: int32 [T*B+1], weights: fp32 [T*E, 128],
// hash_size_cumsum: int32 [T+1], out: fp32 [B, T*128]
//
// One warp per bag; lane = one float4 (16B) of the 512B row.
// Row gathers via cp.async.cg into per-warp smem staging (zero data regs):
// issue up to 8 rows back-to-back, wait_group 0, drain from smem
// (thread-local slots, no barriers).
// Fast path for bag size == 20 (this dataset): straight-line waves 8/8/4,
// no predication. launch_bounds(128,14) -> <=36 regs, 14 blocks/SM (87% occ).

#define EMB_D    128
#define SLOTS    8            // rows in flight per warp per wave
#define WARPS_PB 4            // 128 threads/block; smem = 4*8*512B = 16KB

__global__ void __launch_bounds__(128, 14) tbe_fwd_kernel(
    const int*   __restrict__ indices,
    const int*   __restrict__ offsets,
    const float* __restrict__ weights,
    const int*   __restrict__ hsc,
    float*       __restrict__ out,
    int batch, int n_tables, int num_bags)
{
    // 4 warps * 8 slots * 32 lanes * 16B = 16 KB
    __shared__ float4 buf[WARPS_PB * SLOTS * 32];

    const int warp_global = (blockIdx.x * blockDim.x + threadIdx.x) >> 5;
    const int lane = threadIdx.x & 31;
    const int wib  = (threadIdx.x >> 5);
    if (warp_global >= num_bags) return;

    float4* mybuf = buf + wib * (SLOTS * 32) + lane;   // slot s at mybuf[s*32]
    const unsigned sbase = (unsigned)__cvta_generic_to_shared(mybuf);

    const int seg   = warp_global;
    const int table = seg / batch;
    const int b     = seg - table * batch;

    const int base  = hsc[table];          // T*E <= 4M, fits int32
    const int start = offsets[seg];
    const int end   = offsets[seg + 1];
    const int len   = end - start;

    const float4* __restrict__ wv = reinterpret_cast<const float4*>(weights);

    float4 a0 = make_float4(0.f, 0.f, 0.f, 0.f);
    float4 a1 = make_float4(0.f, 0.f, 0.f, 0.f);
    float4 a2 = make_float4(0.f, 0.f, 0.f, 0.f);
    float4 a3 = make_float4(0.f, 0.f, 0.f, 0.f);

    // straight-line wave: issue CNT cp.asyncs, wait, drain (no predication)
    #define ISSUE_WAVE(KOFF, CNT)                                              \
        do {                                                                   \
            _Pragma("unroll")                                                  \
            for (int s = 0; s < (CNT); s++) {                                  \
                const unsigned row =                                           \
                    (unsigned)(__shfl_sync(0xffffffffu, myidx, (KOFF) + s) + base); \
                asm volatile("cp.async.cg.shared.global [%0], [%1], 16;\n"     \
                             :: "r"(sbase + s * 512u),                         \
                                "l"(wv + (size_t)row * 32u + lane));           \
            }                                                                  \
            asm volatile("cp.async.commit_group;\n");                          \
            asm volatile("cp.async.wait_group 0;\n" ::: "memory");             \
            _Pragma("unroll")                                                  \
            for (int s = 0; s < (CNT); s += 4) {                               \
                { const float4 v = mybuf[(s)*32];                              \
                  a0.x+=v.x; a0.y+=v.y; a0.z+=v.z; a0.w+=v.w; }               \
                if (s+1 < (CNT)) { const float4 v = mybuf[(s+1)*32];           \
                  a1.x+=v.x; a1.y+=v.y; a1.z+=v.z; a1.w+=v.w; }               \
                if (s+2 < (CNT)) { const float4 v = mybuf[(s+2)*32];           \
                  a2.x+=v.x; a2.y+=v.y; a2.z+=v.z; a2.w+=v.w; }               \
                if (s+3 < (CNT)) { const float4 v = mybuf[(s+3)*32];           \
                  a3.x+=v.x; a3.y+=v.y; a3.z+=v.z; a3.w+=v.w; }               \
            }                                                                  \
        } while (0)

    if (len == 20) {
        // fast path: fixed bag size, single index load, exact waves 8/8/4
        const int myidx = (lane < 20) ? indices[start + lane] : 0;
        ISSUE_WAVE(0, 8);
        ISSUE_WAVE(8, 8);
        ISSUE_WAVE(16, 4);
    } else {
        // generic fallback: chunked, predicated
        for (int chunk = start; chunk < end; chunk += 32) {
            const int cnt = min(32, end - chunk);
            const int myidx = (lane < cnt) ? indices[chunk + lane] : 0;

            for (int k = 0; k < cnt; k += SLOTS) {
                const int ns = min(SLOTS, cnt - k);
                #pragma unroll
                for (int s = 0; s < SLOTS; s++) {
                    if (s < ns) {
                        const unsigned row =
                            (unsigned)(__shfl_sync(0xffffffffu, myidx, k + s) + base);
                        asm volatile("cp.async.cg.shared.global [%0], [%1], 16;\n"
                                     :: "r"(sbase + s * 512u),
                                        "l"(wv + (size_t)row * 32u + lane));
                    }
                }
                asm volatile("cp.async.commit_group;\n");
                asm volatile("cp.async.wait_group 0;\n" ::: "memory");
                #pragma unroll
                for (int s = 0; s < SLOTS; s += 4) {
                    if (s < ns) { const float4 v = mybuf[s*32];
                        a0.x+=v.x; a0.y+=v.y; a0.z+=v.z; a0.w+=v.w; }
                    if (s+1 < ns) { const float4 v = mybuf[(s+1)*32];
                        a1.x+=v.x; a1.y+=v.y; a1.z+=v.z; a1.w+=v.w; }
                    if (s+2 < ns) { const float4 v = mybuf[(s+2)*32];
                        a2.x+=v.x; a2.y+=v.y; a2.z+=v.z; a2.w+=v.w; }
                    if (s+3 < ns) { const float4 v = mybuf[(s+3)*32];
                        a3.x+=v.x; a3.y+=v.y; a3.z+=v.z; a3.w+=v.w; }
                }
            }
        }
    }
    #undef ISSUE_WAVE

    float4 acc;
    acc.x = (a0.x + a1.x) + (a2.x + a3.x);
    acc.y = (a0.y + a1.y) + (a2.y + a3.y);
    acc.z = (a0.z + a1.z) + (a2.z + a3.z);
    acc.w = (a0.w + a1.w) + (a2.w + a3.w);

    float4* o = reinterpret_cast<float4*>(
        out + (size_t)b * ((size_t)n_tables * EMB_D) + (size_t)table * EMB_D);
    o[lane] = acc;
}

extern "C" void kernel_launch(void* const* d_in, const int* in_sizes, int n_in,
                              void* d_out, int out_size)
{
    const int*   indices = (const int*)d_in[0];
    const int*   offsets = (const int*)d_in[1];
    const float* weights = (const float*)d_in[2];
    const int*   hsc     = (const int*)d_in[3];
    float* out = (float*)d_out;

    const int num_bags = in_sizes[1] - 1;   // T*B
    const int n_tables = in_sizes[3] - 1;   // T
    const int batch    = num_bags / n_tables;

    const int blocks = (num_bags + WARPS_PB - 1) / WARPS_PB;

    tbe_fwd_kernel<<<blocks, WARPS_PB * 32>>>(
        indices, offsets, weights, hsc, out, batch, n_tables, num_bags);
}

// round 10
// speedup vs baseline: 1.0417x; 1.0417x over previous
#include <cuda_runtime.h>
#include <cstdint>

// Table-batched embedding bag, SUM pooling.
// indices: int32 [T*B*L], offsets: int32 [T*B+1], weights: fp32 [T*E, 128],
// hash_size_cumsum: int32 [T+1], out: fp32 [B, T*128]
//
// One warp per bag; lane = one float4 (16B) of the 512B row.
// cp.async.cg into per-warp smem staging (16 slots = two 8-row banks).
// SOFTWARE-PIPELINED: both 8-row waves issued up front; while draining wave
// g, wave g+1 is still in flight (wait_group 1), so the warp never has zero
// loads outstanding. L=20 fast path is fully straight-line.

#define EMB_D    128
#define WARPS_PB 4            // 128 threads/block; smem = 4*16*512B = 32KB

__global__ void __launch_bounds__(128, 7) tbe_fwd_kernel(
    const int*   __restrict__ indices,
    const int*   __restrict__ offsets,
    const float* __restrict__ weights,
    const int*   __restrict__ hsc,
    float*       __restrict__ out,
    int batch, int n_tables, int num_bags)
{
    // 4 warps * 16 slots * 32 lanes * 16B = 32 KB
    __shared__ float4 buf[WARPS_PB * 16 * 32];

    const int warp_global = (blockIdx.x * blockDim.x + threadIdx.x) >> 5;
    const int lane = threadIdx.x & 31;
    const int wib  = (threadIdx.x >> 5);
    if (warp_global >= num_bags) return;

    float4* mybuf = buf + wib * (16 * 32) + lane;   // slot s at mybuf[s*32]
    const unsigned sbase = (unsigned)__cvta_generic_to_shared(mybuf);

    const int seg   = warp_global;
    const int table = seg / batch;
    const int b     = seg - table * batch;

    const int base  = hsc[table];          // T*E <= 4M, fits int32
    const int start = offsets[seg];
    const int end   = offsets[seg + 1];
    const int len   = end - start;

    const float4* __restrict__ wv = reinterpret_cast<const float4*>(weights);

    float4 a0 = make_float4(0.f, 0.f, 0.f, 0.f);
    float4 a1 = make_float4(0.f, 0.f, 0.f, 0.f);
    float4 a2 = make_float4(0.f, 0.f, 0.f, 0.f);
    float4 a3 = make_float4(0.f, 0.f, 0.f, 0.f);

    // issue CNT rows starting at bag pos KOFF into slots SLOT0..SLOT0+CNT-1
    #define ISSUE(KOFF, SLOT0, CNT)                                            \
        do {                                                                   \
            _Pragma("unroll")                                                  \
            for (int s = 0; s < (CNT); s++) {                                  \
                const unsigned row =                                           \
                    (unsigned)(__shfl_sync(0xffffffffu, myidx, (KOFF) + s) + base); \
                asm volatile("cp.async.cg.shared.global [%0], [%1], 16;\n"     \
                             :: "r"(sbase + ((SLOT0) + s) * 512u),             \
                                "l"(wv + (size_t)row * 32u + lane));           \
            }                                                                  \
            asm volatile("cp.async.commit_group;\n");                          \
        } while (0)

    #define DRAIN(SLOT0, CNT)                                                  \
        do {                                                                   \
            _Pragma("unroll")                                                  \
            for (int s = 0; s < (CNT); s += 4) {                               \
                { const float4 v = mybuf[((SLOT0)+s)*32];                      \
                  a0.x+=v.x; a0.y+=v.y; a0.z+=v.z; a0.w+=v.w; }               \
                if (s+1 < (CNT)) { const float4 v = mybuf[((SLOT0)+s+1)*32];   \
                  a1.x+=v.x; a1.y+=v.y; a1.z+=v.z; a1.w+=v.w; }               \
                if (s+2 < (CNT)) { const float4 v = mybuf[((SLOT0)+s+2)*32];   \
                  a2.x+=v.x; a2.y+=v.y; a2.z+=v.z; a2.w+=v.w; }               \
                if (s+3 < (CNT)) { const float4 v = mybuf[((SLOT0)+s+3)*32];   \
                  a3.x+=v.x; a3.y+=v.y; a3.z+=v.z; a3.w+=v.w; }               \
            }                                                                  \
        } while (0)

    if (len == 20) {
        // fast path: single index load; pipelined waves 8,8,4
        const int myidx = (lane < 20) ? indices[start + lane] : 0;
        ISSUE(0, 0, 8);                                     // w0 -> slots 0..7
        ISSUE(8, 8, 8);                                     // w1 -> slots 8..15
        asm volatile("cp.async.wait_group 1;\n" ::: "memory");  // w0 ready, w1 in flight
        DRAIN(0, 8);
        ISSUE(16, 0, 4);                                    // w2 -> slots 0..3
        asm volatile("cp.async.wait_group 1;\n" ::: "memory");  // w1 ready, w2 in flight
        DRAIN(8, 8);
        asm volatile("cp.async.wait_group 0;\n" ::: "memory");  // w2 ready
        DRAIN(0, 4);
    } else {
        // generic fallback: flat issue-8 / wait / drain per group
        for (int chunk = start; chunk < end; chunk += 32) {
            const int cnt = min(32, end - chunk);
            const int myidx = (lane < cnt) ? indices[chunk + lane] : 0;

            for (int k = 0; k < cnt; k += 8) {
                const int ns = min(8, cnt - k);
                #pragma unroll
                for (int s = 0; s < 8; s++) {
                    if (s < ns) {
                        const unsigned row =
                            (unsigned)(__shfl_sync(0xffffffffu, myidx, k + s) + base);
                        asm volatile("cp.async.cg.shared.global [%0], [%1], 16;\n"
                                     :: "r"(sbase + s * 512u),
                                        "l"(wv + (size_t)row * 32u + lane));
                    }
                }
                asm volatile("cp.async.commit_group;\n");
                asm volatile("cp.async.wait_group 0;\n" ::: "memory");
                #pragma unroll
                for (int s = 0; s < 8; s += 4) {
                    if (s < ns) { const float4 v = mybuf[s*32];
                        a0.x+=v.x; a0.y+=v.y; a0.z+=v.z; a0.w+=v.w; }
                    if (s+1 < ns) { const float4 v = mybuf[(s+1)*32];
                        a1.x+=v.x; a1.y+=v.y; a1.z+=v.z; a1.w+=v.w; }
                    if (s+2 < ns) { const float4 v = mybuf[(s+2)*32];
                        a2.x+=v.x; a2.y+=v.y; a2.z+=v.z; a2.w+=v.w; }
                    if (s+3 < ns) { const float4 v = mybuf[(s+3)*32];
                        a3.x+=v.x; a3.y+=v.y; a3.z+=v.z; a3.w+=v.w; }
                }
            }
        }
    }
    #undef ISSUE
    #undef DRAIN

    float4 acc;
    acc.x = (a0.x + a1.x) + (a2.x + a3.x);
    acc.y = (a0.y + a1.y) + (a2.y + a3.y);
    acc.z = (a0.z + a1.z) + (a2.z + a3.z);
    acc.w = (a0.w + a1.w) + (a2.w + a3.w);

    float4* o = reinterpret_cast<float4*>(
        out + (size_t)b * ((size_t)n_tables * EMB_D) + (size_t)table * EMB_D);
    o[lane] = acc;
}

extern "C" void kernel_launch(void* const* d_in, const int* in_sizes, int n_in,
                              void* d_out, int out_size)
{
    const int*   indices = (const int*)d_in[0];
    const int*   offsets = (const int*)d_in[1];
    const float* weights = (const float*)d_in[2];
    const int*   hsc     = (const int*)d_in[3];
    float* out = (float*)d_out;

    const int num_bags = in_sizes[1] - 1;   // T*B
    const int n_tables = in_sizes[3] - 1;   // T
    const int batch    = num_bags / n_tables;

    const int blocks = (num_bags + WARPS_PB - 1) / WARPS_PB;

    tbe_fwd_kernel<<<blocks, WARPS_PB * 32>>>(
        indices, offsets, weights, hsc, out, batch, n_tables, num_bags);
}

// round 11
// speedup vs baseline: 1.0746x; 1.0316x over previous
#include <cuda_runtime.h>
#include <cstdint>

// Table-batched embedding bag, SUM pooling.
// indices: int32 [T*B*L], offsets: int32 [T*B+1], weights: fp32 [T*E, 128],
// hash_size_cumsum: int32 [T+1], out: fp32 [B, T*128]
//
// One warp per bag; lane = one float4 (16B) of the 512B row.
// cp.async.cg into per-warp smem staging (12 slots). Software-pipelined
// L=20 fast path: waves 8,4,8 with wait_group 1, so the warp always has
// >=4 rows in flight. 12 slots -> 24KB/block; launch_bounds(128,8) ->
// 8 blocks/SM (50% occ, ~1.6x R10) with the same pipelined schedule.

#define EMB_D    128
#define NSLOT    12           // staging slots per warp
#define WARPS_PB 4            // 128 threads/block; smem = 4*12*512B = 24KB

__global__ void __launch_bounds__(128, 8) tbe_fwd_kernel(
    const int*   __restrict__ indices,
    const int*   __restrict__ offsets,
    const float* __restrict__ weights,
    const int*   __restrict__ hsc,
    float*       __restrict__ out,
    int batch, int n_tables, int num_bags)
{
    // 4 warps * 12 slots * 32 lanes * 16B = 24 KB
    __shared__ float4 buf[WARPS_PB * NSLOT * 32];

    const int warp_global = (blockIdx.x * blockDim.x + threadIdx.x) >> 5;
    const int lane = threadIdx.x & 31;
    const int wib  = (threadIdx.x >> 5);
    if (warp_global >= num_bags) return;

    float4* mybuf = buf + wib * (NSLOT * 32) + lane;   // slot s at mybuf[s*32]
    const unsigned sbase = (unsigned)__cvta_generic_to_shared(mybuf);

    const int seg   = warp_global;
    const int table = seg / batch;
    const int b     = seg - table * batch;

    const int base  = hsc[table];          // T*E <= 4M, fits int32
    const int start = offsets[seg];
    const int end   = offsets[seg + 1];
    const int len   = end - start;

    const float4* __restrict__ wv = reinterpret_cast<const float4*>(weights);

    float4 a0 = make_float4(0.f, 0.f, 0.f, 0.f);
    float4 a1 = make_float4(0.f, 0.f, 0.f, 0.f);
    float4 a2 = make_float4(0.f, 0.f, 0.f, 0.f);
    float4 a3 = make_float4(0.f, 0.f, 0.f, 0.f);

    // issue CNT rows starting at bag pos KOFF into slots SLOT0..SLOT0+CNT-1
    #define ISSUE(KOFF, SLOT0, CNT)                                            \
        do {                                                                   \
            _Pragma("unroll")                                                  \
            for (int s = 0; s < (CNT); s++) {                                  \
                const unsigned row =                                           \
                    (unsigned)(__shfl_sync(0xffffffffu, myidx, (KOFF) + s) + base); \
                asm volatile("cp.async.cg.shared.global [%0], [%1], 16;\n"     \
                             :: "r"(sbase + ((SLOT0) + s) * 512u),             \
                                "l"(wv + (size_t)row * 32u + lane));           \
            }                                                                  \
            asm volatile("cp.async.commit_group;\n");                          \
        } while (0)

    #define DRAIN(SLOT0, CNT)                                                  \
        do {                                                                   \
            _Pragma("unroll")                                                  \
            for (int s = 0; s < (CNT); s += 4) {                               \
                { const float4 v = mybuf[((SLOT0)+s)*32];                      \
                  a0.x+=v.x; a0.y+=v.y; a0.z+=v.z; a0.w+=v.w; }               \
                if (s+1 < (CNT)) { const float4 v = mybuf[((SLOT0)+s+1)*32];   \
                  a1.x+=v.x; a1.y+=v.y; a1.z+=v.z; a1.w+=v.w; }               \
                if (s+2 < (CNT)) { const float4 v = mybuf[((SLOT0)+s+2)*32];   \
                  a2.x+=v.x; a2.y+=v.y; a2.z+=v.z; a2.w+=v.w; }               \
                if (s+3 < (CNT)) { const float4 v = mybuf[((SLOT0)+s+3)*32];   \
                  a3.x+=v.x; a3.y+=v.y; a3.z+=v.z; a3.w+=v.w; }               \
            }                                                                  \
        } while (0)

    if (len == 20) {
        // fast path: single index load; pipelined waves 8,4,8 over 12 slots
        const int myidx = (lane < 20) ? indices[start + lane] : 0;
        ISSUE(0, 0, 8);                                     // w0 -> slots 0..7
        ISSUE(8, 8, 4);                                     // w1 -> slots 8..11
        asm volatile("cp.async.wait_group 1;\n" ::: "memory");  // w0 ready, w1 in flight
        DRAIN(0, 8);
        ISSUE(12, 0, 8);                                    // w2 -> slots 0..7
        asm volatile("cp.async.wait_group 1;\n" ::: "memory");  // w1 ready, w2 in flight
        DRAIN(8, 4);
        asm volatile("cp.async.wait_group 0;\n" ::: "memory");  // w2 ready
        DRAIN(0, 8);
    } else {
        // generic fallback: flat issue-8 / wait / drain per group
        for (int chunk = start; chunk < end; chunk += 32) {
            const int cnt = min(32, end - chunk);
            const int myidx = (lane < cnt) ? indices[chunk + lane] : 0;

            for (int k = 0; k < cnt; k += 8) {
                const int ns = min(8, cnt - k);
                #pragma unroll
                for (int s = 0; s < 8; s++) {
                    if (s < ns) {
                        const unsigned row =
                            (unsigned)(__shfl_sync(0xffffffffu, myidx, k + s) + base);
                        asm volatile("cp.async.cg.shared.global [%0], [%1], 16;\n"
                                     :: "r"(sbase + s * 512u),
                                        "l"(wv + (size_t)row * 32u + lane));
                    }
                }
                asm volatile("cp.async.commit_group;\n");
                asm volatile("cp.async.wait_group 0;\n" ::: "memory");
                #pragma unroll
                for (int s = 0; s < 8; s += 4) {
                    if (s < ns) { const float4 v = mybuf[s*32];
                        a0.x+=v.x; a0.y+=v.y; a0.z+=v.z; a0.w+=v.w; }
                    if (s+1 < ns) { const float4 v = mybuf[(s+1)*32];
                        a1.x+=v.x; a1.y+=v.y; a1.z+=v.z; a1.w+=v.w; }
                    if (s+2 < ns) { const float4 v = mybuf[(s+2)*32];
                        a2.x+=v.x; a2.y+=v.y; a2.z+=v.z; a2.w+=v.w; }
                    if (s+3 < ns) { const float4 v = mybuf[(s+3)*32];
                        a3.x+=v.x; a3.y+=v.y; a3.z+=v.z; a3.w+=v.w; }
                }
            }
        }
    }
    #undef ISSUE
    #undef DRAIN

    float4 acc;
    acc.x = (a0.x + a1.x) + (a2.x + a3.x);
    acc.y = (a0.y + a1.y) + (a2.y + a3.y);
    acc.z = (a0.z + a1.z) + (a2.z + a3.z);
    acc.w = (a0.w + a1.w) + (a2.w + a3.w);

    float4* o = reinterpret_cast<float4*>(
        out + (size_t)b * ((size_t)n_tables * EMB_D) + (size_t)table * EMB_D);
    o[lane] = acc;
}

extern "C" void kernel_launch(void* const* d_in, const int* in_sizes, int n_in,
                              void* d_out, int out_size)
{
    const int*   indices = (const int*)d_in[0];
    const int*   offsets = (const int*)d_in[1];
    const float* weights = (const float*)d_in[2];
    const int*   hsc     = (const int*)d_in[3];
    float* out = (float*)d_out;

    const int num_bags = in_sizes[1] - 1;   // T*B
    const int n_tables = in_sizes[3] - 1;   // T
    const int batch    = num_bags / n_tables;

    const int blocks = (num_bags + WARPS_PB - 1) / WARPS_PB;

    tbe_fwd_kernel<<<blocks, WARPS_PB * 32>>>(
        indices, offsets, weights, hsc, out, batch, n_tables, num_bags);
}